// round 4
// baseline (speedup 1.0000x reference)
#include <cuda_runtime.h>
#include <cuda_bf16.h>
#include <math.h>

// ---------------------------------------------------------------------------
// 2-layer LSTM, B=16, T=1024, D=H=512, fp32.
// Round 3: atomic-free distributed-flag grid barrier + per-warp h staging.
// ---------------------------------------------------------------------------

#define Bsz   16
#define Tlen  1024
#define Hdim  512
#define G4H   2048
#define NBLK  128

__device__ float g_gx[(size_t)Bsz * Tlen * G4H];
__device__ float g_out0[(size_t)Bsz * Tlen * Hdim];
__device__ float g_hbuf[2][Bsz * Hdim];
__device__ unsigned int g_arrive[NBLK * 8];   // one 32B-strided flag per CTA
__device__ unsigned int g_gen;

union F4U2 { float4 f; ulonglong2 u; };

__device__ __forceinline__ unsigned long long ffma2(unsigned long long a,
                                                    unsigned long long b,
                                                    unsigned long long c) {
    unsigned long long d;
    asm("fma.rn.f32x2 %0, %1, %2, %3;" : "=l"(d) : "l"(a), "l"(b), "l"(c));
    return d;
}
__device__ __forceinline__ unsigned long long dup2(float x) {
    unsigned long long r;
    asm("mov.b64 %0, {%1, %1};" : "=l"(r) : "f"(x));
    return r;
}
__device__ __forceinline__ void unpk2(unsigned long long v, float& lo, float& hi) {
    asm("mov.b64 {%0, %1}, %2;" : "=f"(lo), "=f"(hi) : "l"(v));
}

// ---------------------------------------------------------------------------
// GEMM (NT), unchanged.
// ---------------------------------------------------------------------------
#define GP 132

__global__ __launch_bounds__(256, 2) void gemm_nt_bias(
    const float* __restrict__ A, const float* __restrict__ B,
    const float* __restrict__ bias, float* __restrict__ C,
    int M, int N, int K)
{
    __shared__ float As[32][GP];
    __shared__ float Bs[32][GP];

    const int tid = threadIdx.x;
    const int m0 = blockIdx.y * 128;
    const int n0 = blockIdx.x * 128;
    const int tx = tid & 15;
    const int ty = tid >> 4;
    const int lrow = tid >> 3;
    const int lkq  = tid & 7;

    unsigned long long acc[8][4];
#pragma unroll
    for (int i = 0; i < 8; i++)
#pragma unroll
        for (int j = 0; j < 4; j++) acc[i][j] = 0ull;

    for (int k0 = 0; k0 < K; k0 += 32) {
#pragma unroll
        for (int i = 0; i < 4; i++) {
            int row = lrow + 32 * i;
            float4 va = *(const float4*)&A[(size_t)(m0 + row) * K + k0 + lkq * 4];
            As[lkq * 4 + 0][row] = va.x;
            As[lkq * 4 + 1][row] = va.y;
            As[lkq * 4 + 2][row] = va.z;
            As[lkq * 4 + 3][row] = va.w;
            float4 vb = *(const float4*)&B[(size_t)(n0 + row) * K + k0 + lkq * 4];
            Bs[lkq * 4 + 0][row] = vb.x;
            Bs[lkq * 4 + 1][row] = vb.y;
            Bs[lkq * 4 + 2][row] = vb.z;
            Bs[lkq * 4 + 3][row] = vb.w;
        }
        __syncthreads();

#pragma unroll
        for (int k = 0; k < 32; k++) {
            float4 a0 = *(const float4*)&As[k][ty * 8];
            float4 a1 = *(const float4*)&As[k][ty * 8 + 4];
            F4U2 b0, b1;
            b0.f = *(const float4*)&Bs[k][tx * 8];
            b1.f = *(const float4*)&Bs[k][tx * 8 + 4];
            unsigned long long bb[4] = { b0.u.x, b0.u.y, b1.u.x, b1.u.y };
            float av[8] = { a0.x, a0.y, a0.z, a0.w, a1.x, a1.y, a1.z, a1.w };
#pragma unroll
            for (int i = 0; i < 8; i++) {
                unsigned long long a2 = dup2(av[i]);
#pragma unroll
                for (int j = 0; j < 4; j++)
                    acc[i][j] = ffma2(a2, bb[j], acc[i][j]);
            }
        }
        __syncthreads();
    }

    float bv[8];
    {
        float4 t0 = *(const float4*)&bias[n0 + tx * 8];
        float4 t1 = *(const float4*)&bias[n0 + tx * 8 + 4];
        bv[0]=t0.x; bv[1]=t0.y; bv[2]=t0.z; bv[3]=t0.w;
        bv[4]=t1.x; bv[5]=t1.y; bv[6]=t1.z; bv[7]=t1.w;
    }
#pragma unroll
    for (int i = 0; i < 8; i++) {
        int row = m0 + ty * 8 + i;
        float v[8];
#pragma unroll
        for (int j = 0; j < 4; j++) unpk2(acc[i][j], v[2 * j], v[2 * j + 1]);
        float4 o0 = make_float4(v[0]+bv[0], v[1]+bv[1], v[2]+bv[2], v[3]+bv[3]);
        float4 o1 = make_float4(v[4]+bv[4], v[5]+bv[5], v[6]+bv[6], v[7]+bv[7]);
        *(float4*)&C[(size_t)row * N + n0 + tx * 8]     = o0;
        *(float4*)&C[(size_t)row * N + n0 + tx * 8 + 4] = o1;
    }
}

// ---------------------------------------------------------------------------
// Scan. Thread (wid=tid>>5, ksl=(tid>>4)&1, r=tid&15).
// Warp wid owns k-range [wid*64, wid*64+64): stages its own h slice into a
// private smem region (syncwarp only). W in registers. Flag-tree barrier.
// ---------------------------------------------------------------------------
__device__ __forceinline__ float sigm_(float x) { return 1.0f / (1.0f + expf(-x)); }

// smem floats: h 8*1088=8704 | part 5120 | gate 256 | gxs 256 | c 64 | bias 16
#define SCAN_SMEM ((8704 + 5120 + 256 + 256 + 64 + 16) * 4)

__global__ __launch_bounds__(256, 1) void lstm_scan(
    const float* __restrict__ gx,     // [B*T, 4H]
    const float* __restrict__ w_hh,   // [4H, 512]
    const float* __restrict__ b_hh,   // [4H]
    const float* __restrict__ h0,     // [B, 512]
    const float* __restrict__ c0,     // [B, 512]
    float* __restrict__ outs,         // [B*T, 512] or nullptr
    float* __restrict__ h_final)      // [B, 512]
{
    extern __shared__ float smem[];
    float* h_all  = smem;                  // 8 warps * 1088 (16 rows * 68)
    float* part   = h_all + 8704;          // 5120
    float* gate_s = part + 5120;           // 256
    float* gxs_f  = gate_s + 256;          // 256
    float* c_s    = gxs_f + 256;           // 64
    float* bias_s = c_s + 64;              // 16

    const int tid  = threadIdx.x;
    const int lane = tid & 31;
    const int wid  = tid >> 5;             // warp = k-range owner
    const int ksl  = (tid >> 4) & 1;       // sub-slice within warp
    const int r    = tid & 15;             // gate-row within CTA
    const int jb   = blockIdx.x * 4;
    const int kb   = ksl * 4;              // float offset within 8-float group

    float* hw = h_all + wid * 1088;        // this warp's h region [b][64k], pad 68

    // launch-phase base (monotonic across launches/replays)
    const unsigned int base = *(volatile unsigned int*)&g_gen;

    // ---- persistent: W slice into registers (16 f32x2) ----
    unsigned long long w2[16];
    {
        const int grow = (r >> 2) * Hdim + jb + (r & 3);
        const float* wrow = &w_hh[(size_t)grow * Hdim + wid * 64];
#pragma unroll
        for (int kp = 0; kp < 8; kp++) {
            F4U2 t; t.f = *(const float4*)&wrow[kp * 8 + kb];
            w2[2 * kp]     = t.u.x;
            w2[2 * kp + 1] = t.u.y;
        }
    }
    if (tid < 16) bias_s[tid] = b_hh[(tid >> 2) * Hdim + jb + (tid & 3)];
    if (tid < 64) {
        int jj = tid >> 4, bb = tid & 15;
        c_s[tid] = c0[bb * Hdim + jb + jj];
    }
    __syncthreads();

    // prefetch gx for t=0
    float4 gxv = make_float4(0.f, 0.f, 0.f, 0.f);
    if (tid < 64) {
        int gg = tid >> 4, bb = tid & 15;
        gxv = __ldcg((const float4*)&gx[(size_t)(bb * Tlen) * G4H + gg * Hdim + jb]);
    }

    for (int t = 0; t < Tlen; t++) {
        // ---- per-warp h staging (own k-slice only; no CTA sync) ----
        const float4* hsrc4 = (t == 0) ? (const float4*)h0
                                       : (const float4*)g_hbuf[t & 1];
#pragma unroll
        for (int i = 0; i < 8; i++) {
            int idx = lane + 32 * i;           // 0..255
            int bb = idx >> 4, q = idx & 15;   // q: float4 within warp's 64-k range
            float4 v = __ldcg(&hsrc4[bb * 128 + wid * 16 + q]);
            *(float4*)&hw[bb * 68 + q * 4] = v;
        }
        __syncwarp();

        // ---- dot: W regs x h broadcast, LDS.128 ----
        unsigned long long acc2[16];
#pragma unroll
        for (int b = 0; b < 16; b++) acc2[b] = 0ull;
#pragma unroll 2
        for (int kp = 0; kp < 8; kp++) {
#pragma unroll
            for (int b = 0; b < 16; b++) {
                F4U2 h4; h4.f = *(const float4*)&hw[b * 68 + kp * 8 + kb];
                acc2[b] = ffma2(w2[2 * kp],     h4.u.x, acc2[b]);
                acc2[b] = ffma2(w2[2 * kp + 1], h4.u.y, acc2[b]);
            }
        }

        // ---- partials: part[ks*320 + r*20 + b], ks = wid*2+ksl ----
        {
            const int ks = wid * 2 + ksl;
            float vals[16];
#pragma unroll
            for (int b = 0; b < 16; b++) {
                float lo, hi; unpk2(acc2[b], lo, hi);
                vals[b] = lo + hi;
            }
            float4* p4 = (float4*)&part[ks * 320 + r * 20];
            p4[0] = make_float4(vals[0], vals[1], vals[2], vals[3]);
            p4[1] = make_float4(vals[4], vals[5], vals[6], vals[7]);
            p4[2] = make_float4(vals[8], vals[9], vals[10], vals[11]);
            p4[3] = make_float4(vals[12], vals[13], vals[14], vals[15]);
        }
        __syncthreads();

        // ---- reduce over ks; thread (r2, b2) owns gate[r2][b2] ----
        {
            int r2 = tid >> 4, b2 = tid & 15;
            float g = 0.f;
#pragma unroll
            for (int k2 = 0; k2 < 16; k2++)
                g += part[k2 * 320 + r2 * 20 + b2];
            gate_s[r2 * 16 + b2] = g;
        }
        if (tid < 64) *(float4*)&gxs_f[tid * 4] = gxv;
        __syncthreads();

        // ---- cell update ----
        if (tid < 64) {
            int jj = tid >> 4, bb = tid & 15;
            float vi = gate_s[(0  + jj) * 16 + bb] + gxs_f[((0  + bb) << 2) + jj] + bias_s[jj];
            float vf = gate_s[(4  + jj) * 16 + bb] + gxs_f[((16 + bb) << 2) + jj] + bias_s[4 + jj];
            float vg = gate_s[(8  + jj) * 16 + bb] + gxs_f[((32 + bb) << 2) + jj] + bias_s[8 + jj];
            float vo = gate_s[(12 + jj) * 16 + bb] + gxs_f[((48 + bb) << 2) + jj] + bias_s[12 + jj];
            float ig = sigm_(vi);
            float fg = sigm_(vf);
            float gg = tanhf(vg);
            float og = sigm_(vo);
            float c  = fg * c_s[tid] + ig * gg;
            c_s[tid] = c;
            float h  = og * tanhf(c);
            int col = jb + jj;
            g_hbuf[(t + 1) & 1][bb * Hdim + col] = h;
            if (outs) outs[(size_t)(bb * Tlen + t) * Hdim + col] = h;
            if (t == Tlen - 1) h_final[bb * Hdim + col] = h;
            __threadfence();
        }

        // prefetch gx for t+1 (hides under barrier wait)
        if (tid < 64 && t + 1 < Tlen) {
            int gg = tid >> 4, bb = tid & 15;
            gxv = __ldcg((const float4*)&gx[(size_t)(bb * Tlen + (t + 1)) * G4H + gg * Hdim + jb]);
        }

        if (t == Tlen - 1) break;

        // ---- atomic-free grid barrier ----
        __syncthreads();                       // all cell writes + fences done
        const unsigned int p = base + (unsigned int)t + 1u;
        if (tid == 0)
            *(volatile unsigned int*)&g_arrive[blockIdx.x * 8] = p;
        if (blockIdx.x == 0) {
            if (tid < NBLK) {
                while (*(volatile unsigned int*)&g_arrive[tid * 8] != p) { }
            }
            __syncthreads();
            if (tid == 0) {
                __threadfence();
                *(volatile unsigned int*)&g_gen = p;
            }
        }
        if (lane == 0) {
            while (*(volatile unsigned int*)&g_gen != p) { }
        }
        __syncwarp();
    }
}

// ---------------------------------------------------------------------------
extern "C" void kernel_launch(void* const* d_in, const int* in_sizes, int n_in,
                              void* d_out, int out_size)
{
    const float* x     = (const float*)d_in[0];
    const float* h0    = (const float*)d_in[1];
    const float* c0    = (const float*)d_in[2];
    const float* w_ih0 = (const float*)d_in[3];
    const float* w_hh0 = (const float*)d_in[4];
    const float* b_ih0 = (const float*)d_in[5];
    const float* b_hh0 = (const float*)d_in[6];
    const float* w_ih1 = (const float*)d_in[7];
    const float* w_hh1 = (const float*)d_in[8];
    const float* b_ih1 = (const float*)d_in[9];
    const float* b_hh1 = (const float*)d_in[10];
    float* out = (float*)d_out;

    void* p;
    cudaGetSymbolAddress(&p, g_gx);   float* gx   = (float*)p;
    cudaGetSymbolAddress(&p, g_out0); float* out0 = (float*)p;

    cudaFuncSetAttribute(lstm_scan, cudaFuncAttributeMaxDynamicSharedMemorySize,
                         SCAN_SMEM);

    const int M = Bsz * Tlen;
    dim3 ggrid(G4H / 128, M / 128);

    gemm_nt_bias<<<ggrid, 256>>>(x, w_ih0, b_ih0, gx, M, G4H, Hdim);
    lstm_scan<<<NBLK, 256, SCAN_SMEM>>>(gx, w_hh0, b_hh0,
                                        h0, c0, out0, out);
    gemm_nt_bias<<<ggrid, 256>>>(out0, w_ih1, b_ih1, gx, M, G4H, Hdim);
    lstm_scan<<<NBLK, 256, SCAN_SMEM>>>(gx, w_hh1, b_hh1,
                                        h0 + Bsz * Hdim, c0 + Bsz * Hdim,
                                        nullptr, out + Bsz * Hdim);
}